// round 6
// baseline (speedup 1.0000x reference)
#include <cuda_runtime.h>

// MultiScaleTrendDirectionLoss — fused EMA + sign-mismatch masked MSE.
// pred, target: [32, 8192, 64] fp32. Output: scalar fp32.
//
// R4: CHUNK=256/HALO=65 cuts redundant-halo DRAM traffic 1.76x -> 1.25x
// (R3 ncu showed halo reads all missing L2: 234MB moved vs 134MB unique).
// Batch-of-8 register prefetch keeps 16 LDGs in flight per warp so 14
// warps/SM still covers DRAM latency. TPB=64 -> 1024 blocks ~ 6.9/SM,
// balanced single wave.

#define Bn 32
#define Tn 8192
#define Dn 64
#define CHUNK 256
#define HALO 65                     // warm iters = 64 (multiple of 8)
#define NCHUNK (Tn / CHUNK)         // 32
#define NROWS (Bn * NCHUNK)         // 1024
#define NWARPS (NROWS * 2)          // 2048 (two d-halves per row)
#define TPB 64
#define WPB (TPB / 32)              // 2
#define NBLK (NWARPS / WPB)         // 1024

__device__ float g_partial[NWARPS];
__device__ unsigned int g_done = 0;

__global__ __launch_bounds__(TPB) void msl_fused(const float* __restrict__ pred,
                                                 const float* __restrict__ tgt,
                                                 float* __restrict__ out)
{
    const int lane = threadIdx.x & 31;
    const int wid  = threadIdx.x >> 5;
    const int gw   = blockIdx.x * WPB + wid;   // global warp id
    const int row  = gw >> 1;                  // (b, chunk)
    const int half = gw & 1;
    const int b  = row >> 5;                   // row / NCHUNK (NCHUNK == 32)
    const int c  = row & 31;                   // row % NCHUNK
    const int cs = c * CHUNK;
    const int t0 = (c == 0) ? 0 : (cs - HALO);
    const int d  = half * 32 + lane;

    const float* __restrict__ pp = pred + ((size_t)(b * Tn + t0)) * Dn + d;
    const float* __restrict__ qq = tgt  + ((size_t)(b * Tn + t0)) * Dn + d;

    const float ALPHA[3] = {0.1f, 0.3f, 0.5f};

    // Seed EMA state with element at t0 (exact for chunk 0; halo warm-up else —
    // (0.9)^64 ~ 1.2e-3 residual, mapping to ~1e-5 in the final scalar).
    float x0 = *pp;
    float y0 = *qq;
    float pe[3], te[3], acc[3];
#pragma unroll
    for (int k = 0; k < 3; ++k) { pe[k] = x0; te[k] = y0; acc[k] = 0.0f; }
    pp += Dn;
    qq += Dn;

    const int nwarm = (c == 0) ? 0 : (HALO - 1);   // 0 or 64
    const int nacc  = (c == 0) ? (CHUNK - 1) : CHUNK;

    // ---- Warm-up: batches of 8, loads hoisted into register arrays (MLP=16).
    for (int i = 0; i < nwarm; i += 8) {
        float xv[8], yv[8];
#pragma unroll
        for (int j = 0; j < 8; ++j) { xv[j] = pp[j * Dn]; yv[j] = qq[j * Dn]; }
        pp += 8 * Dn; qq += 8 * Dn;
#pragma unroll
        for (int j = 0; j < 8; ++j) {
#pragma unroll
            for (int k = 0; k < 3; ++k) {
                pe[k] = fmaf(ALPHA[k], xv[j] - pe[k], pe[k]);
                te[k] = fmaf(ALPHA[k], yv[j] - te[k], te[k]);
            }
        }
    }

    // ---- Accumulation. sign(pe_t - pe_{t-1}) == sign(x_t - pe_{t-1}) since
    // alpha > 0, so the mismatch test is dx*dy < 0 on the FMA operands.
    const int nacc8 = nacc & ~7;
    int i = 0;
    for (; i < nacc8; i += 8) {
        float xv[8], yv[8];
#pragma unroll
        for (int j = 0; j < 8; ++j) { xv[j] = pp[j * Dn]; yv[j] = qq[j * Dn]; }
        pp += 8 * Dn; qq += 8 * Dn;
#pragma unroll
        for (int j = 0; j < 8; ++j) {
#pragma unroll
            for (int k = 0; k < 3; ++k) {
                float dx = xv[j] - pe[k];
                float dy = yv[j] - te[k];
                pe[k] = fmaf(ALPHA[k], dx, pe[k]);
                te[k] = fmaf(ALPHA[k], dy, te[k]);
                float e = pe[k] - te[k];
                if (dx * dy < 0.0f) acc[k] = fmaf(e, e, acc[k]);
            }
        }
    }
    for (; i < nacc; ++i) {                      // remainder (7 iters, chunk 0 only)
        float xv = *pp, yv = *qq;
        pp += Dn; qq += Dn;
#pragma unroll
        for (int k = 0; k < 3; ++k) {
            float dx = xv - pe[k];
            float dy = yv - te[k];
            pe[k] = fmaf(ALPHA[k], dx, pe[k]);
            te[k] = fmaf(ALPHA[k], dy, te[k]);
            float e = pe[k] - te[k];
            if (dx * dy < 0.0f) acc[k] = fmaf(e, e, acc[k]);
        }
    }

    // Per-warp deterministic reduction -> one partial per warp.
    float local = 0.5f * acc[0] + 0.3f * acc[1] + 0.2f * acc[2];
#pragma unroll
    for (int off = 16; off > 0; off >>= 1)
        local += __shfl_down_sync(0xffffffffu, local, off);
    if (lane == 0) g_partial[gw] = local;

    // ---- Last-block-done final reduction (deterministic fixed-order sum) ----
    __syncthreads();
    __shared__ unsigned int s_last;
    if (threadIdx.x == 0) {
        __threadfence();
        s_last = (atomicAdd(&g_done, 1u) == (unsigned)(NBLK - 1));
    }
    __syncthreads();
    if (!s_last) return;

    __threadfence();
    __shared__ float s[TPB];
    volatile float* vp = g_partial;
    float sum = 0.0f;
#pragma unroll
    for (int j = 0; j < NWARPS / TPB; ++j)       // 32 fixed-order adds/thread
        sum += vp[threadIdx.x * (NWARPS / TPB) + j];
    s[threadIdx.x] = sum;
    __syncthreads();
    if (threadIdx.x < 32) {
        float v = s[threadIdx.x] + s[threadIdx.x + 32];
#pragma unroll
        for (int off = 16; off > 0; off >>= 1)
            v += __shfl_down_sync(0xffffffffu, v, off);
        if (threadIdx.x == 0) {
            out[0] = v * (1.0f / (8191.0f * 2048.0f));  // mean over (T-1), then B*D
            g_done = 0;  // reset for next graph replay
        }
    }
}

extern "C" void kernel_launch(void* const* d_in, const int* in_sizes, int n_in,
                              void* d_out, int out_size)
{
    const float* pred = (const float*)d_in[0];
    const float* tgt  = (const float*)d_in[1];
    msl_fused<<<NBLK, TPB>>>(pred, tgt, (float*)d_out);
}

// round 7
// speedup vs baseline: 1.5013x; 1.5013x over previous
#include <cuda_runtime.h>

// MultiScaleTrendDirectionLoss — fused EMA + sign-mismatch masked MSE.
// pred, target: [32, 8192, 64] fp32. Output: scalar fp32.
//
// R5 = R3's proven envelope (CHUNK=128, 4096 warps, TPB=128,
// __launch_bounds__(128,8) -> regs~40 with live prefetch arrays) plus:
//   - HALO 97 -> 65 (traffic factor 1.76x -> 1.49x; R4 proved accuracy ok)
//   - software-pipelined ping-pong batches of 4: next batch's 8 LDGs issue
//     before computing the current batch (R3's load duty cycle was ~50%).

#define Bn 32
#define Tn 8192
#define Dn 64
#define CHUNK 128
#define HALO 65                     // warm iters = 64
#define NCHUNK (Tn / CHUNK)         // 64
#define NROWS (Bn * NCHUNK)         // 2048
#define NWARPS (NROWS * 2)          // 4096 (two d-halves per row)
#define TPB 128
#define WPB (TPB / 32)              // 4
#define NBLK (NWARPS / WPB)         // 1024
#define NBATCH ((HALO - 1 + CHUNK) / 4)   // 48 batches of 4 (c > 0)
#define WARMB ((HALO - 1) / 4)            // first 16 batches: warm-up only

__device__ float g_partial[NWARPS];
__device__ unsigned int g_done = 0;

__global__ __launch_bounds__(TPB, 8) void msl_fused(const float* __restrict__ pred,
                                                    const float* __restrict__ tgt,
                                                    float* __restrict__ out)
{
    const int lane = threadIdx.x & 31;
    const int wid  = threadIdx.x >> 5;
    const int gw   = blockIdx.x * WPB + wid;   // global warp id
    const int row  = gw >> 1;                  // (b, chunk)
    const int half = gw & 1;
    const int b  = row >> 6;                   // row / NCHUNK
    const int c  = row & 63;                   // row % NCHUNK
    const int cs = c * CHUNK;
    const int t0 = (c == 0) ? 0 : (cs - HALO);
    const int d  = half * 32 + lane;

    const float* __restrict__ pp = pred + ((size_t)(b * Tn + t0)) * Dn + d;
    const float* __restrict__ qq = tgt  + ((size_t)(b * Tn + t0)) * Dn + d;

    const float ALPHA[3] = {0.1f, 0.3f, 0.5f};

    // Seed EMA state with element at t0 (exact for chunk 0; halo warm-up else —
    // (0.9)^64 ~ 1.2e-3 state residual -> ~1e-6 in the final scalar, measured).
    float x0 = *pp;
    float y0 = *qq;
    float pe[3], te[3], acc[3];
#pragma unroll
    for (int k = 0; k < 3; ++k) { pe[k] = x0; te[k] = y0; acc[k] = 0.0f; }
    pp += Dn;
    qq += Dn;

    if (c == 0) {
        // 32 of 4096 warps: simple scalar path, t = 1 .. 127, all accumulated.
        for (int i = 0; i < CHUNK - 1; ++i, pp += Dn, qq += Dn) {
            float xv = *pp, yv = *qq;
#pragma unroll
            for (int k = 0; k < 3; ++k) {
                float dx = xv - pe[k];
                float dy = yv - te[k];
                pe[k] = fmaf(ALPHA[k], dx, pe[k]);
                te[k] = fmaf(ALPHA[k], dy, te[k]);
                float e = pe[k] - te[k];
                if (dx * dy < 0.0f) acc[k] = fmaf(e, e, acc[k]);
            }
        }
    } else {
        // Pipelined path: 48 batches of 4 steps; batches [0,16) warm-up only.
        // sign(pe_t - pe_{t-1}) == sign(x_t - pe_{t-1}) for alpha > 0, so the
        // mismatch test is dx*dy < 0 on the FMA operands.
        float xa[4], ya[4], xb[4], yb[4];

#define LOADB(xv, yv)                                                     \
        do {                                                              \
            _Pragma("unroll")                                             \
            for (int j = 0; j < 4; ++j) {                                 \
                xv[j] = pp[j * Dn];                                       \
                yv[j] = qq[j * Dn];                                       \
            }                                                             \
            pp += 4 * Dn; qq += 4 * Dn;                                   \
        } while (0)

#define COMPB(xv, yv, doacc)                                              \
        do {                                                              \
            _Pragma("unroll")                                             \
            for (int j = 0; j < 4; ++j) {                                 \
                _Pragma("unroll")                                         \
                for (int k = 0; k < 3; ++k) {                             \
                    float dx = xv[j] - pe[k];                             \
                    float dy = yv[j] - te[k];                             \
                    pe[k] = fmaf(ALPHA[k], dx, pe[k]);                    \
                    te[k] = fmaf(ALPHA[k], dy, te[k]);                    \
                    if (doacc) {                                          \
                        float e = pe[k] - te[k];                          \
                        if (dx * dy < 0.0f) acc[k] = fmaf(e, e, acc[k]);  \
                    }                                                     \
                }                                                         \
            }                                                             \
        } while (0)

        LOADB(xa, ya);                         // prologue: batch 0 in flight
        for (int bt = 0; bt < NBATCH - 2; bt += 2) {
            LOADB(xb, yb);                     // issue batch bt+1 loads
            COMPB(xa, ya, (bt >= WARMB));      // compute batch bt
            LOADB(xa, ya);                     // issue batch bt+2 loads
            COMPB(xb, yb, (bt + 1 >= WARMB));  // compute batch bt+1
        }
        LOADB(xb, yb);                         // epilogue: last two batches
        COMPB(xa, ya, true);
        COMPB(xb, yb, true);
#undef LOADB
#undef COMPB
    }

    // Per-warp deterministic reduction -> one partial per warp.
    float local = 0.5f * acc[0] + 0.3f * acc[1] + 0.2f * acc[2];
#pragma unroll
    for (int off = 16; off > 0; off >>= 1)
        local += __shfl_down_sync(0xffffffffu, local, off);
    if (lane == 0) g_partial[gw] = local;

    // ---- Last-block-done final reduction (deterministic fixed-order sum) ----
    __syncthreads();
    __shared__ unsigned int s_last;
    if (threadIdx.x == 0) {
        __threadfence();
        s_last = (atomicAdd(&g_done, 1u) == (unsigned)(NBLK - 1));
    }
    __syncthreads();
    if (!s_last) return;

    __threadfence();
    __shared__ float s[TPB];
    volatile float* vp = g_partial;
    float sum = 0.0f;
#pragma unroll
    for (int j = 0; j < NWARPS / TPB; ++j)       // 32 fixed-order adds/thread
        sum += vp[threadIdx.x * (NWARPS / TPB) + j];
    s[threadIdx.x] = sum;
    __syncthreads();
#pragma unroll
    for (int off = TPB / 2; off >= 32; off >>= 1) {
        if (threadIdx.x < off) s[threadIdx.x] += s[threadIdx.x + off];
        __syncthreads();
    }
    if (threadIdx.x < 32) {
        float v = s[threadIdx.x];
#pragma unroll
        for (int off = 16; off > 0; off >>= 1)
            v += __shfl_down_sync(0xffffffffu, v, off);
        if (threadIdx.x == 0) {
            out[0] = v * (1.0f / (8191.0f * 2048.0f));  // mean over (T-1), then B*D
            g_done = 0;  // reset for next graph replay
        }
    }
}

extern "C" void kernel_launch(void* const* d_in, const int* in_sizes, int n_in,
                              void* d_out, int out_size)
{
    const float* pred = (const float*)d_in[0];
    const float* tgt  = (const float*)d_in[1];
    msl_fused<<<NBLK, TPB>>>(pred, tgt, (float*)d_out);
}